// round 6
// baseline (speedup 1.0000x reference)
#include <cuda_runtime.h>
#include <cuda_fp16.h>
#include <math.h>

#define EMB   1024
#define HID   2048
#define VOCAB 50257
#define T     256
#define ROWS_PER_BLK 16
#define NBLK1 ((VOCAB + ROWS_PER_BLK - 1) / ROWS_PER_BLK)   // 3142
#define MAXCAND 256

// Persistent device state (allocation-free scratch).
__device__ float g_h[2][HID];
__device__ __half g_h_half[HID];
__device__ float g_c[HID];
__device__ unsigned long long g_amax[T];    // EXACT packed argmax per step
__device__ unsigned long long g_amax2[T];   // approx packed argmax (fp16 pass)
__device__ int g_ticket[T];
__device__ float g_hnorm2[T];               // ||h||^2 per step
__device__ unsigned g_wmax2;                // max row-norm^2 of W_out (as ordered uint)
__device__ __half g_Wout_h[VOCAB * HID];    // fp16 W_out (~206MB)

__device__ __forceinline__ unsigned long long pack_key(float v, int row) {
    unsigned ub = __float_as_uint(v);
    ub = (ub & 0x80000000u) ? ~ub : (ub | 0x80000000u);
    return ((unsigned long long)ub << 32) |
           (unsigned long long)(0xFFFFFFFFu - (unsigned)row);
}
__device__ __forceinline__ float unpack_val(unsigned long long key) {
    unsigned t = (unsigned)(key >> 32);
    unsigned orig = (t & 0x80000000u) ? (t ^ 0x80000000u) : ~t;
    return __uint_as_float(orig);
}

// ---------------------------------------------------------------------------
// Convert W_out to fp16 AND compute max row-norm^2 (block-per-row).
// ---------------------------------------------------------------------------
__global__ void __launch_bounds__(256) convert_wout(const float* __restrict__ W) {
    __shared__ float swsum[8];
    float maxn = 0.0f;

    for (int r = blockIdx.x; r < VOCAB; r += gridDim.x) {
        const float4* __restrict__ src = (const float4*)(W + (size_t)r * HID);
        __half2* __restrict__ dst = (__half2*)(g_Wout_h + (size_t)r * HID);
        float ss = 0.0f;
        #pragma unroll
        for (int i = threadIdx.x; i < HID / 4; i += 256) {   // 2 iters
            float4 v = src[i];
            dst[2 * i]     = __floats2half2_rn(v.x, v.y);
            dst[2 * i + 1] = __floats2half2_rn(v.z, v.w);
            ss += v.x * v.x + v.y * v.y + v.z * v.z + v.w * v.w;
        }
        #pragma unroll
        for (int off = 16; off; off >>= 1)
            ss += __shfl_down_sync(0xFFFFFFFFu, ss, off);
        if ((threadIdx.x & 31) == 0) swsum[threadIdx.x >> 5] = ss;
        __syncthreads();
        if (threadIdx.x == 0) {
            float tot = 0.0f;
            #pragma unroll
            for (int i = 0; i < 8; i++) tot += swsum[i];
            if (tot > maxn) maxn = tot;
        }
        __syncthreads();
    }
    if (threadIdx.x == 0)
        atomicMax(&g_wmax2, __float_as_uint(maxn));   // positive floats: uint-ordered
}

__global__ void init_kernel() {
    int i = blockIdx.x * blockDim.x + threadIdx.x;
    if (i < HID) {
        g_h[0][i] = 0.0f;
        g_h[1][i] = 0.0f;
        g_h_half[i] = __float2half(0.0f);
        g_c[i]    = 0.0f;
    }
    if (i < T) { g_amax[i] = 0ULL; g_amax2[i] = 0ULL; g_ticket[i] = 0; g_hnorm2[i] = 0.0f; }
    if (i == 0) g_wmax2 = 0u;
}

// ---------------------------------------------------------------------------
// LSTM step (full fp32): warp-per-(gate,j). 1024 blocks x 256 threads.
// Tail writes h (fp32 + fp16) and accumulates ||h||^2 for the error bound.
// ---------------------------------------------------------------------------
__global__ void __launch_bounds__(256) lstm_step_kernel(
    const float* __restrict__ emb,
    const float* __restrict__ W_ih,
    const float* __restrict__ W_hh,
    const float* __restrict__ b_ih,
    const float* __restrict__ b_hh,
    int step)
{
    __shared__ float sx[EMB];
    __shared__ float sh[HID];
    __shared__ float sg[2][4];

    int tok = 0;
    if (step > 0)
        tok = (int)(0xFFFFFFFFu - (unsigned)(g_amax[step - 1] & 0xFFFFFFFFull));

    const float* __restrict__ hprev = g_h[step & 1];
    float* __restrict__ hnext       = g_h[(step + 1) & 1];

    const float* __restrict__ xrow = emb + (size_t)tok * EMB;
    for (int i = threadIdx.x; i < EMB; i += 256) sx[i] = xrow[i];
    for (int i = threadIdx.x; i < HID; i += 256) sh[i] = hprev[i];
    __syncthreads();

    const int wid  = threadIdx.x >> 5;
    const int lane = threadIdx.x & 31;
    const int jl   = wid >> 2;
    const int gate = wid & 3;
    const int j    = blockIdx.x * 2 + jl;
    const int row  = gate * HID + j;

    float a = 0.f;
    const float4* __restrict__ w1  = (const float4*)(W_ih + (size_t)row * EMB);
    const float4* __restrict__ s4x = (const float4*)sx;
    #pragma unroll
    for (int k = 0; k < EMB / 128; k++) {
        float4 w = w1[lane + 32 * k];
        float4 v = s4x[lane + 32 * k];
        a += w.x * v.x + w.y * v.y + w.z * v.z + w.w * v.w;
    }
    const float4* __restrict__ w2  = (const float4*)(W_hh + (size_t)row * HID);
    const float4* __restrict__ s4h = (const float4*)sh;
    #pragma unroll
    for (int k = 0; k < HID / 128; k++) {
        float4 w = w2[lane + 32 * k];
        float4 v = s4h[lane + 32 * k];
        a += w.x * v.x + w.y * v.y + w.z * v.z + w.w * v.w;
    }

    #pragma unroll
    for (int off = 16; off; off >>= 1)
        a += __shfl_down_sync(0xFFFFFFFFu, a, off);

    if (lane == 0) sg[jl][gate] = a;
    __syncthreads();

    if (threadIdx.x < 2) {
        const int jj = blockIdx.x * 2 + threadIdx.x;
        float ipre = sg[threadIdx.x][0] + b_ih[jj]           + b_hh[jj];
        float fpre = sg[threadIdx.x][1] + b_ih[HID + jj]     + b_hh[HID + jj];
        float gpre = sg[threadIdx.x][2] + b_ih[2 * HID + jj] + b_hh[2 * HID + jj];
        float opre = sg[threadIdx.x][3] + b_ih[3 * HID + jj] + b_hh[3 * HID + jj];

        float ig = 1.0f / (1.0f + expf(-ipre));
        float fg = 1.0f / (1.0f + expf(-fpre));
        float gg = tanhf(gpre);
        float og = 1.0f / (1.0f + expf(-opre));

        float c = fg * g_c[jj] + ig * gg;
        float h = og * tanhf(c);
        g_c[jj]      = c;
        hnext[jj]    = h;
        g_h_half[jj] = __float2half(h);
        atomicAdd(&g_hnorm2[step], h * h);
    }
}

// ---------------------------------------------------------------------------
// Logits: fp16 weights, warp-per-row streaming. AtomicMax folds the approx
// argmax; LAST block (ticket) computes a PROVABLE fp16-error window
// E = 2^-9 * ||W_row||_max * ||h||  (|approx-exact| <= 2^-10*||w||*||h|| by
// Cauchy-Schwarz; extra 2x margin), collects rows with approx >= max-2E,
// recomputes them exactly in fp32, writes exact first-index argmax.
// ---------------------------------------------------------------------------
__global__ void __launch_bounds__(512) logits_kernel(
    const float* __restrict__ W_out,
    const float* __restrict__ b_out,
    float* __restrict__ out,
    int step)
{
    __shared__ unsigned long long skey[ROWS_PER_BLK];
    __shared__ int s_islast;
    __shared__ int s_ncand;
    __shared__ int s_cand[MAXCAND];
    __shared__ unsigned long long s_ckey[MAXCAND];

    const int wid  = threadIdx.x >> 5;
    const int lane = threadIdx.x & 31;
    const int row  = blockIdx.x * ROWS_PER_BLK + wid;

    float* __restrict__ orow = out + (size_t)step * VOCAB;

    unsigned long long key = 0ULL;
    if (row < VOCAB) {
        const int4* __restrict__ wp = (const int4*)(g_Wout_h + (size_t)row * HID);
        const int4* __restrict__ hp = (const int4*)g_h_half;

        float a = 0.f;
        #pragma unroll
        for (int k = 0; k < HID / 256; k++) {       // 8 iters, 16B each
            int4 w = wp[lane + 32 * k];
            int4 h = hp[lane + 32 * k];
            float2 wf, hf;
            wf = __half22float2(*(__half2*)&w.x); hf = __half22float2(*(__half2*)&h.x);
            a += wf.x * hf.x + wf.y * hf.y;
            wf = __half22float2(*(__half2*)&w.y); hf = __half22float2(*(__half2*)&h.y);
            a += wf.x * hf.x + wf.y * hf.y;
            wf = __half22float2(*(__half2*)&w.z); hf = __half22float2(*(__half2*)&h.z);
            a += wf.x * hf.x + wf.y * hf.y;
            wf = __half22float2(*(__half2*)&w.w); hf = __half22float2(*(__half2*)&h.w);
            a += wf.x * hf.x + wf.y * hf.y;
        }
        #pragma unroll
        for (int off = 16; off; off >>= 1)
            a += __shfl_down_sync(0xFFFFFFFFu, a, off);

        if (lane == 0) {
            float logit = a + b_out[row];
            orow[row] = logit;
            key = pack_key(logit, row);
        }
    }
    if (lane == 0) skey[wid] = key;
    __syncthreads();

    if (threadIdx.x == 0) {
        unsigned long long b = 0ULL;
        #pragma unroll
        for (int i = 0; i < ROWS_PER_BLK; i++) if (skey[i] > b) b = skey[i];
        if (b) atomicMax(&g_amax2[step], b);

        __threadfence();
        int old = atomicAdd(&g_ticket[step], 1);
        s_islast = (old == (int)gridDim.x - 1);
        s_ncand  = 0;
    }
    __syncthreads();
    if (!s_islast) return;

    // ---- last block only ----
    const float E = 0.001953125f *            // 2^-9
                    sqrtf(__uint_as_float(g_wmax2) * g_hnorm2[step]);
    const float thresh = unpack_val(g_amax2[step]) - 2.0f * E;

    for (int r = threadIdx.x; r < VOCAB; r += 512) {
        float v = __ldcg(&orow[r]);
        if (v >= thresh) {
            int p = atomicAdd(&s_ncand, 1);
            if (p < MAXCAND) s_cand[p] = r;
        }
    }
    __syncthreads();

    int nc = s_ncand; if (nc > MAXCAND) nc = MAXCAND;

    const float4* __restrict__ hp32 = (const float4*)g_h[(step + 1) & 1];
    for (int ci = wid; ci < nc; ci += 16) {
        const int r = s_cand[ci];
        const float4* __restrict__ wp = (const float4*)(W_out + (size_t)r * HID);
        float a = 0.f;
        #pragma unroll
        for (int k = 0; k < HID / 128; k++) {
            float4 w = wp[lane + 32 * k];
            float4 v = hp32[lane + 32 * k];
            a += w.x * v.x + w.y * v.y + w.z * v.z + w.w * v.w;
        }
        #pragma unroll
        for (int off = 16; off; off >>= 1)
            a += __shfl_down_sync(0xFFFFFFFFu, a, off);
        if (lane == 0) {
            float logit = a + b_out[r];
            orow[r] = logit;                          // exact overwrite
            s_ckey[ci] = pack_key(logit, r);
        }
    }
    __syncthreads();

    if (threadIdx.x == 0) {
        unsigned long long b = 0ULL;
        for (int i = 0; i < nc; i++) if (s_ckey[i] > b) b = s_ckey[i];
        g_amax[step] = b;
    }
}

// ---------------------------------------------------------------------------
extern "C" void kernel_launch(void* const* d_in, const int* in_sizes, int n_in,
                              void* d_out, int out_size) {
    const float* emb   = (const float*)d_in[0];
    const float* W_ih  = (const float*)d_in[1];
    const float* W_hh  = (const float*)d_in[2];
    const float* b_ih  = (const float*)d_in[3];
    const float* b_hh  = (const float*)d_in[4];
    const float* W_out = (const float*)d_in[5];
    const float* b_out = (const float*)d_in[6];
    float* out = (float*)d_out;

    init_kernel<<<(HID + 255) / 256, 256>>>();
    convert_wout<<<2048, 256>>>(W_out);

    for (int t = 0; t < T; t++) {
        lstm_step_kernel<<<HID / 2, 256>>>(emb, W_ih, W_hh, b_ih, b_hh, t);
        logits_kernel<<<NBLK1, 512>>>(W_out, b_out, out, t);
    }
}

// round 7
// speedup vs baseline: 1.3196x; 1.3196x over previous
#include <cuda_runtime.h>
#include <cuda_fp16.h>
#include <math.h>

#define EMB   1024
#define HID   2048
#define VOCAB 50257
#define T     256
#define ROWS_PER_BLK 16
#define NBLK1 ((VOCAB + ROWS_PER_BLK - 1) / ROWS_PER_BLK)   // 3142
#define MAXCAND 256

// Persistent device state (allocation-free scratch).
__device__ float g_h[2][HID];
__device__ __half g_h_half[HID];
__device__ float g_c[HID];
__device__ unsigned long long g_amax[T];    // EXACT packed argmax per step
__device__ unsigned long long g_amax2[T];   // approx packed argmax (fp16 pass)
__device__ float g_hnorm2[T];               // ||h||^2 per step
__device__ unsigned g_wmax2;                // max row-norm^2 of W_out (ordered uint)
__device__ __half g_Wout_h[VOCAB * HID];    // fp16 W_out (~206MB)

__device__ __forceinline__ unsigned long long pack_key(float v, int row) {
    unsigned ub = __float_as_uint(v);
    ub = (ub & 0x80000000u) ? ~ub : (ub | 0x80000000u);
    return ((unsigned long long)ub << 32) |
           (unsigned long long)(0xFFFFFFFFu - (unsigned)row);
}
__device__ __forceinline__ float unpack_val(unsigned long long key) {
    unsigned t = (unsigned)(key >> 32);
    unsigned orig = (t & 0x80000000u) ? (t ^ 0x80000000u) : ~t;
    return __uint_as_float(orig);
}

// ---------------------------------------------------------------------------
// Convert W_out to fp16 AND compute max row-norm^2 (block-per-row).
// ---------------------------------------------------------------------------
__global__ void __launch_bounds__(256) convert_wout(const float* __restrict__ W) {
    __shared__ float swsum[8];
    float maxn = 0.0f;

    for (int r = blockIdx.x; r < VOCAB; r += gridDim.x) {
        const float4* __restrict__ src = (const float4*)(W + (size_t)r * HID);
        __half2* __restrict__ dst = (__half2*)(g_Wout_h + (size_t)r * HID);
        float ss = 0.0f;
        #pragma unroll
        for (int i = threadIdx.x; i < HID / 4; i += 256) {   // 2 iters
            float4 v = src[i];
            dst[2 * i]     = __floats2half2_rn(v.x, v.y);
            dst[2 * i + 1] = __floats2half2_rn(v.z, v.w);
            ss += v.x * v.x + v.y * v.y + v.z * v.z + v.w * v.w;
        }
        #pragma unroll
        for (int off = 16; off; off >>= 1)
            ss += __shfl_down_sync(0xFFFFFFFFu, ss, off);
        if ((threadIdx.x & 31) == 0) swsum[threadIdx.x >> 5] = ss;
        __syncthreads();
        if (threadIdx.x == 0) {
            float tot = 0.0f;
            #pragma unroll
            for (int i = 0; i < 8; i++) tot += swsum[i];
            if (tot > maxn) maxn = tot;
        }
        __syncthreads();
    }
    if (threadIdx.x == 0)
        atomicMax(&g_wmax2, __float_as_uint(maxn));   // positive floats: uint-ordered
}

__global__ void init_kernel() {
    int i = blockIdx.x * blockDim.x + threadIdx.x;
    if (i < HID) {
        g_h[0][i] = 0.0f;
        g_h[1][i] = 0.0f;
        g_h_half[i] = __float2half(0.0f);
        g_c[i]    = 0.0f;
    }
    if (i < T) { g_amax[i] = 0ULL; g_amax2[i] = 0ULL; g_hnorm2[i] = 0.0f; }
    if (i == 0) g_wmax2 = 0u;
}

// ---------------------------------------------------------------------------
// LSTM step (full fp32): warp-per-(gate,j). 1024 blocks x 256 threads.
// Tail writes h (fp32 + fp16) and accumulates ||h||^2 for the error bound.
// ---------------------------------------------------------------------------
__global__ void __launch_bounds__(256) lstm_step_kernel(
    const float* __restrict__ emb,
    const float* __restrict__ W_ih,
    const float* __restrict__ W_hh,
    const float* __restrict__ b_ih,
    const float* __restrict__ b_hh,
    int step)
{
    __shared__ float sx[EMB];
    __shared__ float sh[HID];
    __shared__ float sg[2][4];

    int tok = 0;
    if (step > 0)
        tok = (int)(0xFFFFFFFFu - (unsigned)(g_amax[step - 1] & 0xFFFFFFFFull));

    const float* __restrict__ hprev = g_h[step & 1];
    float* __restrict__ hnext       = g_h[(step + 1) & 1];

    const float* __restrict__ xrow = emb + (size_t)tok * EMB;
    for (int i = threadIdx.x; i < EMB; i += 256) sx[i] = xrow[i];
    for (int i = threadIdx.x; i < HID; i += 256) sh[i] = hprev[i];
    __syncthreads();

    const int wid  = threadIdx.x >> 5;
    const int lane = threadIdx.x & 31;
    const int jl   = wid >> 2;
    const int gate = wid & 3;
    const int j    = blockIdx.x * 2 + jl;
    const int row  = gate * HID + j;

    float a = 0.f;
    const float4* __restrict__ w1  = (const float4*)(W_ih + (size_t)row * EMB);
    const float4* __restrict__ s4x = (const float4*)sx;
    #pragma unroll
    for (int k = 0; k < EMB / 128; k++) {
        float4 w = w1[lane + 32 * k];
        float4 v = s4x[lane + 32 * k];
        a += w.x * v.x + w.y * v.y + w.z * v.z + w.w * v.w;
    }
    const float4* __restrict__ w2  = (const float4*)(W_hh + (size_t)row * HID);
    const float4* __restrict__ s4h = (const float4*)sh;
    #pragma unroll
    for (int k = 0; k < HID / 128; k++) {
        float4 w = w2[lane + 32 * k];
        float4 v = s4h[lane + 32 * k];
        a += w.x * v.x + w.y * v.y + w.z * v.z + w.w * v.w;
    }

    #pragma unroll
    for (int off = 16; off; off >>= 1)
        a += __shfl_down_sync(0xFFFFFFFFu, a, off);

    if (lane == 0) sg[jl][gate] = a;
    __syncthreads();

    if (threadIdx.x < 2) {
        const int jj = blockIdx.x * 2 + threadIdx.x;
        float ipre = sg[threadIdx.x][0] + b_ih[jj]           + b_hh[jj];
        float fpre = sg[threadIdx.x][1] + b_ih[HID + jj]     + b_hh[HID + jj];
        float gpre = sg[threadIdx.x][2] + b_ih[2 * HID + jj] + b_hh[2 * HID + jj];
        float opre = sg[threadIdx.x][3] + b_ih[3 * HID + jj] + b_hh[3 * HID + jj];

        float ig = 1.0f / (1.0f + expf(-ipre));
        float fg = 1.0f / (1.0f + expf(-fpre));
        float gg = tanhf(gpre);
        float og = 1.0f / (1.0f + expf(-opre));

        float c = fg * g_c[jj] + ig * gg;
        float h = og * tanhf(c);
        g_c[jj]      = c;
        hnext[jj]    = h;
        g_h_half[jj] = __float2half(h);
        atomicAdd(&g_hnorm2[step], h * h);
    }
}

// ---------------------------------------------------------------------------
// Logits (pure streaming): fp16 weights, warp-per-row. Writes approx logits
// and folds the approx argmax (one atomicMax per block). NO tail code here —
// keeps register count low so occupancy stays high.
// ---------------------------------------------------------------------------
__global__ void __launch_bounds__(512) logits_kernel(
    const float* __restrict__ b_out,
    float* __restrict__ out,
    int step)
{
    __shared__ unsigned long long skey[ROWS_PER_BLK];

    const int wid  = threadIdx.x >> 5;
    const int lane = threadIdx.x & 31;
    const int row  = blockIdx.x * ROWS_PER_BLK + wid;

    float* __restrict__ orow = out + (size_t)step * VOCAB;

    unsigned long long key = 0ULL;
    if (row < VOCAB) {
        const int4* __restrict__ wp = (const int4*)(g_Wout_h + (size_t)row * HID);
        const int4* __restrict__ hp = (const int4*)g_h_half;

        float a = 0.f;
        #pragma unroll
        for (int k = 0; k < HID / 256; k++) {       // 8 iters, 16B each
            int4 w = wp[lane + 32 * k];
            int4 h = hp[lane + 32 * k];
            float2 wf, hf;
            wf = __half22float2(*(__half2*)&w.x); hf = __half22float2(*(__half2*)&h.x);
            a += wf.x * hf.x + wf.y * hf.y;
            wf = __half22float2(*(__half2*)&w.y); hf = __half22float2(*(__half2*)&h.y);
            a += wf.x * hf.x + wf.y * hf.y;
            wf = __half22float2(*(__half2*)&w.z); hf = __half22float2(*(__half2*)&h.z);
            a += wf.x * hf.x + wf.y * hf.y;
            wf = __half22float2(*(__half2*)&w.w); hf = __half22float2(*(__half2*)&h.w);
            a += wf.x * hf.x + wf.y * hf.y;
        }
        #pragma unroll
        for (int off = 16; off; off >>= 1)
            a += __shfl_down_sync(0xFFFFFFFFu, a, off);

        if (lane == 0) {
            float logit = a + b_out[row];
            orow[row] = logit;
            key = pack_key(logit, row);
        }
    }
    if (lane == 0) skey[wid] = key;
    __syncthreads();

    if (threadIdx.x == 0) {
        unsigned long long b = 0ULL;
        #pragma unroll
        for (int i = 0; i < ROWS_PER_BLK; i++) if (skey[i] > b) b = skey[i];
        if (b) atomicMax(&g_amax2[step], b);
    }
}

// ---------------------------------------------------------------------------
// Argmax fixup (1 block, 512 thr): provable fp16 error window
// E = 2^-9 * ||W_row||_max * ||h||  (|approx-exact| <= 2^-10*||w||*||h||,
// Cauchy-Schwarz, with 2x margin). Collect rows >= approx_max - 2E from the
// L2-resident approx logits, recompute exactly in fp32, write exact argmax.
// ---------------------------------------------------------------------------
__global__ void __launch_bounds__(512) argmax_fixup(
    const float* __restrict__ W_out,
    const float* __restrict__ b_out,
    float* __restrict__ out,
    int step)
{
    __shared__ int s_ncand;
    __shared__ int s_cand[MAXCAND];
    __shared__ unsigned long long s_ckey[MAXCAND];

    if (threadIdx.x == 0) s_ncand = 0;
    __syncthreads();

    float* __restrict__ orow = out + (size_t)step * VOCAB;

    const float E = 0.001953125f *            // 2^-9
                    sqrtf(__uint_as_float(g_wmax2) * g_hnorm2[step]);
    const float thresh = unpack_val(g_amax2[step]) - 2.0f * E;

    for (int r = threadIdx.x; r < VOCAB; r += 512) {
        float v = __ldcg(&orow[r]);
        if (v >= thresh) {
            int p = atomicAdd(&s_ncand, 1);
            if (p < MAXCAND) s_cand[p] = r;
        }
    }
    __syncthreads();

    int nc = s_ncand; if (nc > MAXCAND) nc = MAXCAND;

    const int wid  = threadIdx.x >> 5;
    const int lane = threadIdx.x & 31;
    const float4* __restrict__ hp32 = (const float4*)g_h[(step + 1) & 1];

    for (int ci = wid; ci < nc; ci += 16) {
        const int r = s_cand[ci];
        const float4* __restrict__ wp = (const float4*)(W_out + (size_t)r * HID);
        float a = 0.f;
        #pragma unroll
        for (int k = 0; k < HID / 128; k++) {
            float4 w = wp[lane + 32 * k];
            float4 v = hp32[lane + 32 * k];
            a += w.x * v.x + w.y * v.y + w.z * v.z + w.w * v.w;
        }
        #pragma unroll
        for (int off = 16; off; off >>= 1)
            a += __shfl_down_sync(0xFFFFFFFFu, a, off);
        if (lane == 0) {
            float logit = a + b_out[r];
            orow[r] = logit;                          // exact overwrite
            s_ckey[ci] = pack_key(logit, r);
        }
    }
    __syncthreads();

    if (threadIdx.x == 0) {
        unsigned long long b = 0ULL;
        for (int i = 0; i < nc; i++) if (s_ckey[i] > b) b = s_ckey[i];
        g_amax[step] = b;
    }
}

// ---------------------------------------------------------------------------
extern "C" void kernel_launch(void* const* d_in, const int* in_sizes, int n_in,
                              void* d_out, int out_size) {
    const float* emb   = (const float*)d_in[0];
    const float* W_ih  = (const float*)d_in[1];
    const float* W_hh  = (const float*)d_in[2];
    const float* b_ih  = (const float*)d_in[3];
    const float* b_hh  = (const float*)d_in[4];
    const float* W_out = (const float*)d_in[5];
    const float* b_out = (const float*)d_in[6];
    float* out = (float*)d_out;

    init_kernel<<<(HID + 255) / 256, 256>>>();
    convert_wout<<<2048, 256>>>(W_out);

    for (int t = 0; t < T; t++) {
        lstm_step_kernel<<<HID / 2, 256>>>(emb, W_ih, W_hh, b_ih, b_hh, t);
        logits_kernel<<<NBLK1, 512>>>(b_out, out, t);
        argmax_fixup<<<1, 512>>>(W_out, b_out, out, t);
    }
}

// round 8
// speedup vs baseline: 1.5079x; 1.1426x over previous
#include <cuda_runtime.h>
#include <cuda_fp16.h>
#include <math.h>

#define EMB   1024
#define HID   2048
#define VOCAB 50257
#define T     256
#define ROWS_PER_BLK 16
#define NBLK1 ((VOCAB + ROWS_PER_BLK - 1) / ROWS_PER_BLK)   // 3142
#define MAXCAND 256

// Persistent device state (allocation-free scratch).
__device__ float g_h[2][HID];
__device__ __half g_h_half[HID];
__device__ float g_c[HID];
__device__ unsigned long long g_amax[T];        // EXACT packed argmax per step
__device__ unsigned long long g_blockbest[NBLK1]; // per-block approx max keys
__device__ float g_hnorm2[T];                   // ||h||^2 per step
__device__ unsigned g_wmax2;                    // max row-norm^2 of W_out (ordered uint)
__device__ __half g_Wout_h[VOCAB * HID];        // fp16 W_out (~206MB)

__device__ __forceinline__ unsigned long long pack_key(float v, int row) {
    unsigned ub = __float_as_uint(v);
    ub = (ub & 0x80000000u) ? ~ub : (ub | 0x80000000u);
    return ((unsigned long long)ub << 32) |
           (unsigned long long)(0xFFFFFFFFu - (unsigned)row);
}
__device__ __forceinline__ float unpack_val(unsigned long long key) {
    unsigned t = (unsigned)(key >> 32);
    unsigned orig = (t & 0x80000000u) ? (t ^ 0x80000000u) : ~t;
    return __uint_as_float(orig);
}

// ---------------------------------------------------------------------------
// Convert W_out to fp16 AND compute max row-norm^2 (block-per-row).
// ---------------------------------------------------------------------------
__global__ void __launch_bounds__(256) convert_wout(const float* __restrict__ W) {
    __shared__ float swsum[8];
    float maxn = 0.0f;

    for (int r = blockIdx.x; r < VOCAB; r += gridDim.x) {
        const float4* __restrict__ src = (const float4*)(W + (size_t)r * HID);
        __half2* __restrict__ dst = (__half2*)(g_Wout_h + (size_t)r * HID);
        float ss = 0.0f;
        #pragma unroll
        for (int i = threadIdx.x; i < HID / 4; i += 256) {   // 2 iters
            float4 v = src[i];
            dst[2 * i]     = __floats2half2_rn(v.x, v.y);
            dst[2 * i + 1] = __floats2half2_rn(v.z, v.w);
            ss += v.x * v.x + v.y * v.y + v.z * v.z + v.w * v.w;
        }
        #pragma unroll
        for (int off = 16; off; off >>= 1)
            ss += __shfl_down_sync(0xFFFFFFFFu, ss, off);
        if ((threadIdx.x & 31) == 0) swsum[threadIdx.x >> 5] = ss;
        __syncthreads();
        if (threadIdx.x == 0) {
            float tot = 0.0f;
            #pragma unroll
            for (int i = 0; i < 8; i++) tot += swsum[i];
            if (tot > maxn) maxn = tot;
        }
        __syncthreads();
    }
    if (threadIdx.x == 0)
        atomicMax(&g_wmax2, __float_as_uint(maxn));   // positive floats: uint-ordered
}

__global__ void init_kernel() {
    int i = blockIdx.x * blockDim.x + threadIdx.x;
    if (i < HID) {
        g_h[0][i] = 0.0f;
        g_h[1][i] = 0.0f;
        g_h_half[i] = __float2half(0.0f);
        g_c[i]    = 0.0f;
    }
    if (i < T) { g_amax[i] = 0ULL; g_hnorm2[i] = 0.0f; }
    if (i == 0) g_wmax2 = 0u;
}

// ---------------------------------------------------------------------------
// LSTM step (full fp32): warp-per-(gate,j). 1024 blocks x 256 threads.
// Tail writes h (fp32 + fp16) and accumulates ||h||^2 for the error bound.
// ---------------------------------------------------------------------------
__global__ void __launch_bounds__(256) lstm_step_kernel(
    const float* __restrict__ emb,
    const float* __restrict__ W_ih,
    const float* __restrict__ W_hh,
    const float* __restrict__ b_ih,
    const float* __restrict__ b_hh,
    int step)
{
    __shared__ float sx[EMB];
    __shared__ float sh[HID];
    __shared__ float sg[2][4];

    int tok = 0;
    if (step > 0)
        tok = (int)(0xFFFFFFFFu - (unsigned)(g_amax[step - 1] & 0xFFFFFFFFull));

    const float* __restrict__ hprev = g_h[step & 1];
    float* __restrict__ hnext       = g_h[(step + 1) & 1];

    const float* __restrict__ xrow = emb + (size_t)tok * EMB;
    for (int i = threadIdx.x; i < EMB; i += 256) sx[i] = xrow[i];
    for (int i = threadIdx.x; i < HID; i += 256) sh[i] = hprev[i];
    __syncthreads();

    const int wid  = threadIdx.x >> 5;
    const int lane = threadIdx.x & 31;
    const int jl   = wid >> 2;
    const int gate = wid & 3;
    const int j    = blockIdx.x * 2 + jl;
    const int row  = gate * HID + j;

    float a = 0.f;
    const float4* __restrict__ w1  = (const float4*)(W_ih + (size_t)row * EMB);
    const float4* __restrict__ s4x = (const float4*)sx;
    #pragma unroll
    for (int k = 0; k < EMB / 128; k++) {
        float4 w = w1[lane + 32 * k];
        float4 v = s4x[lane + 32 * k];
        a += w.x * v.x + w.y * v.y + w.z * v.z + w.w * v.w;
    }
    const float4* __restrict__ w2  = (const float4*)(W_hh + (size_t)row * HID);
    const float4* __restrict__ s4h = (const float4*)sh;
    #pragma unroll
    for (int k = 0; k < HID / 128; k++) {
        float4 w = w2[lane + 32 * k];
        float4 v = s4h[lane + 32 * k];
        a += w.x * v.x + w.y * v.y + w.z * v.z + w.w * v.w;
    }

    #pragma unroll
    for (int off = 16; off; off >>= 1)
        a += __shfl_down_sync(0xFFFFFFFFu, a, off);

    if (lane == 0) sg[jl][gate] = a;
    __syncthreads();

    if (threadIdx.x < 2) {
        const int jj = blockIdx.x * 2 + threadIdx.x;
        float ipre = sg[threadIdx.x][0] + b_ih[jj]           + b_hh[jj];
        float fpre = sg[threadIdx.x][1] + b_ih[HID + jj]     + b_hh[HID + jj];
        float gpre = sg[threadIdx.x][2] + b_ih[2 * HID + jj] + b_hh[2 * HID + jj];
        float opre = sg[threadIdx.x][3] + b_ih[3 * HID + jj] + b_hh[3 * HID + jj];

        float ig = 1.0f / (1.0f + expf(-ipre));
        float fg = 1.0f / (1.0f + expf(-fpre));
        float gg = tanhf(gpre);
        float og = 1.0f / (1.0f + expf(-opre));

        float c = fg * g_c[jj] + ig * gg;
        float h = og * tanhf(c);
        g_c[jj]      = c;
        hnext[jj]    = h;
        g_h_half[jj] = __float2half(h);
        atomicAdd(&g_hnorm2[step], h * h);
    }
}

// ---------------------------------------------------------------------------
// Logits (pure streaming): fp16 weights, warp-per-row. Writes approx logits
// and this block's max key to g_blockbest (plain store, no atomics).
// ---------------------------------------------------------------------------
__global__ void __launch_bounds__(512) logits_kernel(
    const float* __restrict__ b_out,
    float* __restrict__ out,
    int step)
{
    __shared__ unsigned long long skey[ROWS_PER_BLK];

    const int wid  = threadIdx.x >> 5;
    const int lane = threadIdx.x & 31;
    const int row  = blockIdx.x * ROWS_PER_BLK + wid;

    float* __restrict__ orow = out + (size_t)step * VOCAB;

    unsigned long long key = 0ULL;
    if (row < VOCAB) {
        const int4* __restrict__ wp = (const int4*)(g_Wout_h + (size_t)row * HID);
        const int4* __restrict__ hp = (const int4*)g_h_half;

        float a = 0.f;
        #pragma unroll
        for (int k = 0; k < HID / 256; k++) {       // 8 iters, 16B each
            int4 w = wp[lane + 32 * k];
            int4 h = hp[lane + 32 * k];
            float2 wf, hf;
            wf = __half22float2(*(__half2*)&w.x); hf = __half22float2(*(__half2*)&h.x);
            a += wf.x * hf.x + wf.y * hf.y;
            wf = __half22float2(*(__half2*)&w.y); hf = __half22float2(*(__half2*)&h.y);
            a += wf.x * hf.x + wf.y * hf.y;
            wf = __half22float2(*(__half2*)&w.z); hf = __half22float2(*(__half2*)&h.z);
            a += wf.x * hf.x + wf.y * hf.y;
            wf = __half22float2(*(__half2*)&w.w); hf = __half22float2(*(__half2*)&h.w);
            a += wf.x * hf.x + wf.y * hf.y;
        }
        #pragma unroll
        for (int off = 16; off; off >>= 1)
            a += __shfl_down_sync(0xFFFFFFFFu, a, off);

        if (lane == 0) {
            float logit = a + b_out[row];
            orow[row] = logit;
            key = pack_key(logit, row);
        }
    }
    if (lane == 0) skey[wid] = key;
    __syncthreads();

    if (threadIdx.x == 0) {
        unsigned long long b = 0ULL;
        #pragma unroll
        for (int i = 0; i < ROWS_PER_BLK; i++) if (skey[i] > b) b = skey[i];
        g_blockbest[blockIdx.x] = b;
    }
}

// ---------------------------------------------------------------------------
// Argmax fixup (1 block, 512 thr). Scans only the NBLK1 per-block keys:
//  1) global approx max via shared reduction,
//  2) thresh = max - 2E  (E = 2^-9*||W_row||max*||h||; |approx-exact| <=
//     2^-10*||w||*||h|| by Cauchy-Schwarz, 2x margin),
//  3) blocks whose key >= thresh get their 16 approx logits inspected
//     (the exact-argmax row's block always qualifies),
//  4) candidates recomputed exactly in fp32; exact first-index argmax out.
// ---------------------------------------------------------------------------
__global__ void __launch_bounds__(512) argmax_fixup(
    const float* __restrict__ W_out,
    const float* __restrict__ b_out,
    float* __restrict__ out,
    int step)
{
    __shared__ unsigned long long skeys[NBLK1];
    __shared__ unsigned long long sred[512];
    __shared__ int s_ncand;
    __shared__ int s_cand[MAXCAND];
    __shared__ unsigned long long s_ckey[MAXCAND];

    const int tid = threadIdx.x;

    unsigned long long m = 0ULL;
    for (int i = tid; i < NBLK1; i += 512) {
        unsigned long long k = g_blockbest[i];
        skeys[i] = k;
        if (k > m) m = k;
    }
    sred[tid] = m;
    if (tid == 0) s_ncand = 0;
    __syncthreads();
    #pragma unroll
    for (int s = 256; s; s >>= 1) {
        if (tid < s && sred[tid + s] > sred[tid]) sred[tid] = sred[tid + s];
        __syncthreads();
    }

    const float E = 0.001953125f *            // 2^-9
                    sqrtf(__uint_as_float(g_wmax2) * g_hnorm2[step]);
    const float thresh = unpack_val(sred[0]) - 2.0f * E;

    float* __restrict__ orow = out + (size_t)step * VOCAB;

    for (int b = tid; b < NBLK1; b += 512) {
        unsigned long long k = skeys[b];
        if (k != 0ULL && unpack_val(k) >= thresh) {
            const int r0 = b * ROWS_PER_BLK;
            const int r1 = (r0 + ROWS_PER_BLK < VOCAB) ? r0 + ROWS_PER_BLK : VOCAB;
            for (int r = r0; r < r1; r++) {
                float v = __ldcg(&orow[r]);
                if (v >= thresh) {
                    int p = atomicAdd(&s_ncand, 1);
                    if (p < MAXCAND) s_cand[p] = r;
                }
            }
        }
    }
    __syncthreads();

    int nc = s_ncand; if (nc > MAXCAND) nc = MAXCAND;

    const int wid  = tid >> 5;
    const int lane = tid & 31;
    const float4* __restrict__ hp32 = (const float4*)g_h[(step + 1) & 1];

    for (int ci = wid; ci < nc; ci += 16) {
        const int r = s_cand[ci];
        const float4* __restrict__ wp = (const float4*)(W_out + (size_t)r * HID);
        float a = 0.f;
        #pragma unroll
        for (int k = 0; k < HID / 128; k++) {
            float4 w = wp[lane + 32 * k];
            float4 v = hp32[lane + 32 * k];
            a += w.x * v.x + w.y * v.y + w.z * v.z + w.w * v.w;
        }
        #pragma unroll
        for (int off = 16; off; off >>= 1)
            a += __shfl_down_sync(0xFFFFFFFFu, a, off);
        if (lane == 0) {
            float logit = a + b_out[r];
            orow[r] = logit;                          // exact overwrite
            s_ckey[ci] = pack_key(logit, r);
        }
    }
    __syncthreads();

    if (tid == 0) {
        unsigned long long b = 0ULL;
        for (int i = 0; i < nc; i++) if (s_ckey[i] > b) b = s_ckey[i];
        g_amax[step] = b;
    }
}

// ---------------------------------------------------------------------------
extern "C" void kernel_launch(void* const* d_in, const int* in_sizes, int n_in,
                              void* d_out, int out_size) {
    const float* emb   = (const float*)d_in[0];
    const float* W_ih  = (const float*)d_in[1];
    const float* W_hh  = (const float*)d_in[2];
    const float* b_ih  = (const float*)d_in[3];
    const float* b_hh  = (const float*)d_in[4];
    const float* W_out = (const float*)d_in[5];
    const float* b_out = (const float*)d_in[6];
    float* out = (float*)d_out;

    init_kernel<<<(HID + 255) / 256, 256>>>();
    convert_wout<<<2048, 256>>>(W_out);

    for (int t = 0; t < T; t++) {
        lstm_step_kernel<<<HID / 2, 256>>>(emb, W_ih, W_hh, b_ih, b_hh, t);
        logits_kernel<<<NBLK1, 512>>>(b_out, out, t);
        argmax_fixup<<<1, 512>>>(W_out, b_out, out, t);
    }
}

// round 9
// speedup vs baseline: 1.5332x; 1.0168x over previous
#include <cuda_runtime.h>
#include <cuda_fp16.h>
#include <math.h>

#define EMB   1024
#define HID   2048
#define VOCAB 50257
#define T     256
#define ROWS_PER_BLK 8
#define NBLK1 ((VOCAB + ROWS_PER_BLK - 1) / ROWS_PER_BLK)   // 6283
#define MAXCAND 256

// Persistent device state (allocation-free scratch).
__device__ float g_h[2][HID];
__device__ __half g_h_half[HID];
__device__ float g_c[HID];
__device__ unsigned long long g_amax[T];          // EXACT packed argmax per step
__device__ unsigned long long g_blockbest[NBLK1]; // per-block approx max keys
__device__ float g_hnorm2[T];                     // ||h||^2 per step
__device__ unsigned g_wmax2;                      // max row-norm^2 of W_out (ordered uint)
__device__ __half g_Wout_h[VOCAB * HID];          // fp16 W_out (~206MB)

__device__ __forceinline__ unsigned long long pack_key(float v, int row) {
    unsigned ub = __float_as_uint(v);
    ub = (ub & 0x80000000u) ? ~ub : (ub | 0x80000000u);
    return ((unsigned long long)ub << 32) |
           (unsigned long long)(0xFFFFFFFFu - (unsigned)row);
}
__device__ __forceinline__ float unpack_val(unsigned long long key) {
    unsigned t = (unsigned)(key >> 32);
    unsigned orig = (t & 0x80000000u) ? (t ^ 0x80000000u) : ~t;
    return __uint_as_float(orig);
}

// dot of 8 halves (int4-packed) against 8 halves, accumulated in fp32
__device__ __forceinline__ void acc_h8(const int4& w, const int4& h, float& a) {
    float2 wf, hf;
    wf = __half22float2(*(const __half2*)&w.x); hf = __half22float2(*(const __half2*)&h.x);
    a += wf.x * hf.x + wf.y * hf.y;
    wf = __half22float2(*(const __half2*)&w.y); hf = __half22float2(*(const __half2*)&h.y);
    a += wf.x * hf.x + wf.y * hf.y;
    wf = __half22float2(*(const __half2*)&w.z); hf = __half22float2(*(const __half2*)&h.z);
    a += wf.x * hf.x + wf.y * hf.y;
    wf = __half22float2(*(const __half2*)&w.w); hf = __half22float2(*(const __half2*)&h.w);
    a += wf.x * hf.x + wf.y * hf.y;
}

// ---------------------------------------------------------------------------
// Convert W_out to fp16 AND compute max row-norm^2 (block-per-row).
// ---------------------------------------------------------------------------
__global__ void __launch_bounds__(256) convert_wout(const float* __restrict__ W) {
    __shared__ float swsum[8];
    float maxn = 0.0f;

    for (int r = blockIdx.x; r < VOCAB; r += gridDim.x) {
        const float4* __restrict__ src = (const float4*)(W + (size_t)r * HID);
        __half2* __restrict__ dst = (__half2*)(g_Wout_h + (size_t)r * HID);
        float ss = 0.0f;
        #pragma unroll
        for (int i = threadIdx.x; i < HID / 4; i += 256) {
            float4 v = src[i];
            dst[2 * i]     = __floats2half2_rn(v.x, v.y);
            dst[2 * i + 1] = __floats2half2_rn(v.z, v.w);
            ss += v.x * v.x + v.y * v.y + v.z * v.z + v.w * v.w;
        }
        #pragma unroll
        for (int off = 16; off; off >>= 1)
            ss += __shfl_down_sync(0xFFFFFFFFu, ss, off);
        if ((threadIdx.x & 31) == 0) swsum[threadIdx.x >> 5] = ss;
        __syncthreads();
        if (threadIdx.x == 0) {
            float tot = 0.0f;
            #pragma unroll
            for (int i = 0; i < 8; i++) tot += swsum[i];
            if (tot > maxn) maxn = tot;
        }
        __syncthreads();
    }
    if (threadIdx.x == 0)
        atomicMax(&g_wmax2, __float_as_uint(maxn));
}

__global__ void init_kernel() {
    int i = blockIdx.x * blockDim.x + threadIdx.x;
    if (i < HID) {
        g_h[0][i] = 0.0f;
        g_h[1][i] = 0.0f;
        g_h_half[i] = __float2half(0.0f);
        g_c[i]    = 0.0f;
    }
    if (i < T) { g_amax[i] = 0ULL; g_hnorm2[i] = 0.0f; }
    if (i == 0) g_wmax2 = 0u;
}

// ---------------------------------------------------------------------------
// LSTM step (full fp32): warp-per-(gate,j). 1024 blocks x 256 threads.
// Streaming loads (__ldcs) + dual accumulators for chain ILP.
// ---------------------------------------------------------------------------
__global__ void __launch_bounds__(256) lstm_step_kernel(
    const float* __restrict__ emb,
    const float* __restrict__ W_ih,
    const float* __restrict__ W_hh,
    const float* __restrict__ b_ih,
    const float* __restrict__ b_hh,
    int step)
{
    __shared__ float sx[EMB];
    __shared__ float sh[HID];
    __shared__ float sg[2][4];

    int tok = 0;
    if (step > 0)
        tok = (int)(0xFFFFFFFFu - (unsigned)(g_amax[step - 1] & 0xFFFFFFFFull));

    const float* __restrict__ hprev = g_h[step & 1];
    float* __restrict__ hnext       = g_h[(step + 1) & 1];

    const float* __restrict__ xrow = emb + (size_t)tok * EMB;
    for (int i = threadIdx.x; i < EMB; i += 256) sx[i] = xrow[i];
    for (int i = threadIdx.x; i < HID; i += 256) sh[i] = hprev[i];
    __syncthreads();

    const int wid  = threadIdx.x >> 5;
    const int lane = threadIdx.x & 31;
    const int jl   = wid >> 2;
    const int gate = wid & 3;
    const int j    = blockIdx.x * 2 + jl;
    const int row  = gate * HID + j;

    float a0 = 0.f, a1 = 0.f;
    const float4* __restrict__ w1  = (const float4*)(W_ih + (size_t)row * EMB);
    const float4* __restrict__ s4x = (const float4*)sx;
    #pragma unroll
    for (int k = 0; k < EMB / 256; k++) {            // 4 dual-iters
        float4 wa = __ldcs(&w1[lane + 64 * k]);
        float4 wb = __ldcs(&w1[lane + 32 + 64 * k]);
        float4 va = s4x[lane + 64 * k];
        float4 vb = s4x[lane + 32 + 64 * k];
        a0 += wa.x * va.x + wa.y * va.y + wa.z * va.z + wa.w * va.w;
        a1 += wb.x * vb.x + wb.y * vb.y + wb.z * vb.z + wb.w * vb.w;
    }
    const float4* __restrict__ w2  = (const float4*)(W_hh + (size_t)row * HID);
    const float4* __restrict__ s4h = (const float4*)sh;
    #pragma unroll
    for (int k = 0; k < HID / 256; k++) {            // 8 dual-iters
        float4 wa = __ldcs(&w2[lane + 64 * k]);
        float4 wb = __ldcs(&w2[lane + 32 + 64 * k]);
        float4 va = s4h[lane + 64 * k];
        float4 vb = s4h[lane + 32 + 64 * k];
        a0 += wa.x * va.x + wa.y * va.y + wa.z * va.z + wa.w * va.w;
        a1 += wb.x * vb.x + wb.y * vb.y + wb.z * vb.z + wb.w * vb.w;
    }
    float a = a0 + a1;

    #pragma unroll
    for (int off = 16; off; off >>= 1)
        a += __shfl_down_sync(0xFFFFFFFFu, a, off);

    if (lane == 0) sg[jl][gate] = a;
    __syncthreads();

    if (threadIdx.x < 2) {
        const int jj = blockIdx.x * 2 + threadIdx.x;
        float ipre = sg[threadIdx.x][0] + b_ih[jj]           + b_hh[jj];
        float fpre = sg[threadIdx.x][1] + b_ih[HID + jj]     + b_hh[HID + jj];
        float gpre = sg[threadIdx.x][2] + b_ih[2 * HID + jj] + b_hh[2 * HID + jj];
        float opre = sg[threadIdx.x][3] + b_ih[3 * HID + jj] + b_hh[3 * HID + jj];

        float ig = 1.0f / (1.0f + expf(-ipre));
        float fg = 1.0f / (1.0f + expf(-fpre));
        float gg = tanhf(gpre);
        float og = 1.0f / (1.0f + expf(-opre));

        float c = fg * g_c[jj] + ig * gg;
        float h = og * tanhf(c);
        g_c[jj]      = c;
        hnext[jj]    = h;
        g_h_half[jj] = __float2half(h);
        atomicAdd(&g_hnorm2[step], h * h);
    }
}

// ---------------------------------------------------------------------------
// Logits (pure streaming): fp16 weights, warp-per-row, 8 rows / 256 threads.
// h staged in smem; 32B per lane per iter (2x LDG.128) with dual fp32
// accumulators; __ldcs streaming on weights. Per-block max key -> plain store.
// ---------------------------------------------------------------------------
__global__ void __launch_bounds__(256) logits_kernel(
    const float* __restrict__ b_out,
    float* __restrict__ out,
    int step)
{
    __shared__ __half sh[HID];                       // 4KB
    __shared__ unsigned long long skey[ROWS_PER_BLK];

    {   // stage h: 2048 halves = 256 int4 loads, one per thread
        const int4* __restrict__ hg = (const int4*)g_h_half;
        ((int4*)sh)[threadIdx.x] = hg[threadIdx.x];
    }
    __syncthreads();

    const int wid  = threadIdx.x >> 5;
    const int lane = threadIdx.x & 31;
    const int row  = blockIdx.x * ROWS_PER_BLK + wid;

    float* __restrict__ orow = out + (size_t)step * VOCAB;

    unsigned long long key = 0ULL;
    if (row < VOCAB) {
        const int4* __restrict__ wp  = (const int4*)(g_Wout_h + (size_t)row * HID);
        const int4* __restrict__ sh4 = (const int4*)sh;

        float a0 = 0.f, a1 = 0.f;
        #pragma unroll
        for (int k = 0; k < 4; k++) {                // 4 iters x 32B/lane
            int4 w0 = __ldcs(&wp[2 * lane + 64 * k]);
            int4 w1 = __ldcs(&wp[2 * lane + 1 + 64 * k]);
            int4 h0 = sh4[2 * lane + 64 * k];
            int4 h1 = sh4[2 * lane + 1 + 64 * k];
            acc_h8(w0, h0, a0);
            acc_h8(w1, h1, a1);
        }
        float a = a0 + a1;
        #pragma unroll
        for (int off = 16; off; off >>= 1)
            a += __shfl_down_sync(0xFFFFFFFFu, a, off);

        if (lane == 0) {
            float logit = a + b_out[row];
            orow[row] = logit;
            key = pack_key(logit, row);
        }
    }
    if (lane == 0) skey[wid] = key;
    __syncthreads();

    if (threadIdx.x == 0) {
        unsigned long long b = 0ULL;
        #pragma unroll
        for (int i = 0; i < ROWS_PER_BLK; i++) if (skey[i] > b) b = skey[i];
        g_blockbest[blockIdx.x] = b;
    }
}

// ---------------------------------------------------------------------------
// Argmax fixup (1 block, 512 thr). Two L2 passes over the NBLK1 keys:
//  1) global approx max, 2) thresh = max - 2E (provable fp16 window:
//  |approx-exact| <= 2^-10*||w||*||h||, Cauchy-Schwarz, 2x margin),
//  3) qualifying blocks' 8 approx logits inspected, 4) candidates
//  recomputed exactly in fp32 -> exact first-index argmax.
// ---------------------------------------------------------------------------
__global__ void __launch_bounds__(512) argmax_fixup(
    const float* __restrict__ W_out,
    const float* __restrict__ b_out,
    float* __restrict__ out,
    int step)
{
    __shared__ unsigned long long sred[512];
    __shared__ int s_ncand;
    __shared__ int s_cand[MAXCAND];
    __shared__ unsigned long long s_ckey[MAXCAND];

    const int tid = threadIdx.x;

    unsigned long long m = 0ULL;
    for (int i = tid; i < NBLK1; i += 512) {
        unsigned long long k = __ldcg(&g_blockbest[i]);
        if (k > m) m = k;
    }
    sred[tid] = m;
    if (tid == 0) s_ncand = 0;
    __syncthreads();
    #pragma unroll
    for (int s = 256; s; s >>= 1) {
        if (tid < s && sred[tid + s] > sred[tid]) sred[tid] = sred[tid + s];
        __syncthreads();
    }

    const float E = 0.001953125f *            // 2^-9
                    sqrtf(__uint_as_float(g_wmax2) * g_hnorm2[step]);
    const float thresh = unpack_val(sred[0]) - 2.0f * E;

    float* __restrict__ orow = out + (size_t)step * VOCAB;

    for (int b = tid; b < NBLK1; b += 512) {
        unsigned long long k = __ldcg(&g_blockbest[b]);
        if (k != 0ULL && unpack_val(k) >= thresh) {
            const int r0 = b * ROWS_PER_BLK;
            const int r1 = (r0 + ROWS_PER_BLK < VOCAB) ? r0 + ROWS_PER_BLK : VOCAB;
            for (int r = r0; r < r1; r++) {
                float v = __ldcg(&orow[r]);
                if (v >= thresh) {
                    int p = atomicAdd(&s_ncand, 1);
                    if (p < MAXCAND) s_cand[p] = r;
                }
            }
        }
    }
    __syncthreads();

    int nc = s_ncand; if (nc > MAXCAND) nc = MAXCAND;

    const int wid  = tid >> 5;
    const int lane = tid & 31;
    const float4* __restrict__ hp32 = (const float4*)g_h[(step + 1) & 1];

    for (int ci = wid; ci < nc; ci += 16) {
        const int r = s_cand[ci];
        const float4* __restrict__ wp = (const float4*)(W_out + (size_t)r * HID);
        float a = 0.f;
        #pragma unroll
        for (int k = 0; k < HID / 128; k++) {
            float4 w = wp[lane + 32 * k];
            float4 v = hp32[lane + 32 * k];
            a += w.x * v.x + w.y * v.y + w.z * v.z + w.w * v.w;
        }
        #pragma unroll
        for (int off = 16; off; off >>= 1)
            a += __shfl_down_sync(0xFFFFFFFFu, a, off);
        if (lane == 0) {
            float logit = a + b_out[r];
            orow[r] = logit;                          // exact overwrite
            s_ckey[ci] = pack_key(logit, r);
        }
    }
    __syncthreads();

    if (tid == 0) {
        unsigned long long b = 0ULL;
        for (int i = 0; i < nc; i++) if (s_ckey[i] > b) b = s_ckey[i];
        g_amax[step] = b;
    }
}

// ---------------------------------------------------------------------------
extern "C" void kernel_launch(void* const* d_in, const int* in_sizes, int n_in,
                              void* d_out, int out_size) {
    const float* emb   = (const float*)d_in[0];
    const float* W_ih  = (const float*)d_in[1];
    const float* W_hh  = (const float*)d_in[2];
    const float* b_ih  = (const float*)d_in[3];
    const float* b_hh  = (const float*)d_in[4];
    const float* W_out = (const float*)d_in[5];
    const float* b_out = (const float*)d_in[6];
    float* out = (float*)d_out;

    init_kernel<<<(HID + 255) / 256, 256>>>();
    convert_wout<<<2048, 256>>>(W_out);

    for (int t = 0; t < T; t++) {
        lstm_step_kernel<<<HID / 2, 256>>>(emb, W_ih, W_hh, b_ih, b_hh, t);
        logits_kernel<<<NBLK1, 256>>>(b_out, out, t);
        argmax_fixup<<<1, 512>>>(W_out, b_out, out, t);
    }
}

// round 10
// speedup vs baseline: 1.7089x; 1.1146x over previous
#include <cuda_runtime.h>
#include <cuda_fp16.h>
#include <math.h>

#define EMB   1024
#define HID   2048
#define VOCAB 50257
#define T     256
#define ROWS_PER_BLK 8
#define NBLK1 ((VOCAB + ROWS_PER_BLK - 1) / ROWS_PER_BLK)   // 6283
#define MAXCAND 256

// Persistent device state (allocation-free scratch).
__device__ float g_h[2][HID];
__device__ __half g_h_half[HID];
__device__ float g_c[HID];
__device__ unsigned long long g_amax[T];          // EXACT packed argmax per step
__device__ unsigned long long g_amax2[T];         // approx global max key per step
__device__ unsigned long long g_blockbest[NBLK1]; // per-block approx max keys
__device__ float g_hnorm2[T];                     // ||h||^2 per step
__device__ unsigned g_wmax2;                      // max row-norm^2 of W_out (ordered uint)
__device__ __half g_Wout_h[VOCAB * HID];          // fp16 W_out (~206MB)

__device__ __forceinline__ unsigned long long pack_key(float v, int row) {
    unsigned ub = __float_as_uint(v);
    ub = (ub & 0x80000000u) ? ~ub : (ub | 0x80000000u);
    return ((unsigned long long)ub << 32) |
           (unsigned long long)(0xFFFFFFFFu - (unsigned)row);
}
__device__ __forceinline__ float unpack_val(unsigned long long key) {
    unsigned t = (unsigned)(key >> 32);
    unsigned orig = (t & 0x80000000u) ? (t ^ 0x80000000u) : ~t;
    return __uint_as_float(orig);
}

// Packed f32x2 FMA (Blackwell FFMA2): acc = a*b + acc, two lanes at once.
__device__ __forceinline__ void ffma2(unsigned long long& acc,
                                      unsigned long long a, unsigned long long b) {
    asm("fma.rn.f32x2 %0, %1, %2, %3;" : "=l"(acc) : "l"(a), "l"(b), "l"(acc));
}
__device__ __forceinline__ float f32x2_sum(unsigned long long v) {
    float2 f = *reinterpret_cast<float2*>(&v);
    return f.x + f.y;
}
union f4u { float4 f; unsigned long long u[2]; };

// ---------------------------------------------------------------------------
// Convert W_out to fp16 AND compute max row-norm^2 (block-per-row).
// ---------------------------------------------------------------------------
__global__ void __launch_bounds__(256) convert_wout(const float* __restrict__ W) {
    __shared__ float swsum[8];
    float maxn = 0.0f;

    for (int r = blockIdx.x; r < VOCAB; r += gridDim.x) {
        const float4* __restrict__ src = (const float4*)(W + (size_t)r * HID);
        __half2* __restrict__ dst = (__half2*)(g_Wout_h + (size_t)r * HID);
        float ss = 0.0f;
        #pragma unroll
        for (int i = threadIdx.x; i < HID / 4; i += 256) {
            float4 v = src[i];
            dst[2 * i]     = __floats2half2_rn(v.x, v.y);
            dst[2 * i + 1] = __floats2half2_rn(v.z, v.w);
            ss += v.x * v.x + v.y * v.y + v.z * v.z + v.w * v.w;
        }
        #pragma unroll
        for (int off = 16; off; off >>= 1)
            ss += __shfl_down_sync(0xFFFFFFFFu, ss, off);
        if ((threadIdx.x & 31) == 0) swsum[threadIdx.x >> 5] = ss;
        __syncthreads();
        if (threadIdx.x == 0) {
            float tot = 0.0f;
            #pragma unroll
            for (int i = 0; i < 8; i++) tot += swsum[i];
            if (tot > maxn) maxn = tot;
        }
        __syncthreads();
    }
    if (threadIdx.x == 0)
        atomicMax(&g_wmax2, __float_as_uint(maxn));
}

__global__ void init_kernel() {
    int i = blockIdx.x * blockDim.x + threadIdx.x;
    if (i < HID) {
        g_h[0][i] = 0.0f;
        g_h[1][i] = 0.0f;
        g_h_half[i] = __float2half(0.0f);
        g_c[i]    = 0.0f;
    }
    if (i < T) { g_amax[i] = 0ULL; g_amax2[i] = 0ULL; g_hnorm2[i] = 0.0f; }
    if (i == 0) g_wmax2 = 0u;
}

// ---------------------------------------------------------------------------
// LSTM step (full fp32 accuracy): warp-per-(gate,j), FFMA2 packed math.
// ---------------------------------------------------------------------------
__global__ void __launch_bounds__(256) lstm_step_kernel(
    const float* __restrict__ emb,
    const float* __restrict__ W_ih,
    const float* __restrict__ W_hh,
    const float* __restrict__ b_ih,
    const float* __restrict__ b_hh,
    int step)
{
    __shared__ float sx[EMB];
    __shared__ float sh[HID];
    __shared__ float sg[2][4];

    int tok = 0;
    if (step > 0)
        tok = (int)(0xFFFFFFFFu - (unsigned)(g_amax[step - 1] & 0xFFFFFFFFull));

    const float* __restrict__ hprev = g_h[step & 1];
    float* __restrict__ hnext       = g_h[(step + 1) & 1];

    const float* __restrict__ xrow = emb + (size_t)tok * EMB;
    for (int i = threadIdx.x; i < EMB; i += 256) sx[i] = xrow[i];
    for (int i = threadIdx.x; i < HID; i += 256) sh[i] = hprev[i];
    __syncthreads();

    const int wid  = threadIdx.x >> 5;
    const int lane = threadIdx.x & 31;
    const int jl   = wid >> 2;
    const int gate = wid & 3;
    const int j    = blockIdx.x * 2 + jl;
    const int row  = gate * HID + j;

    unsigned long long accA = 0ULL, accB = 0ULL, accC = 0ULL, accD = 0ULL;

    const float4* __restrict__ w1  = (const float4*)(W_ih + (size_t)row * EMB);
    const float4* __restrict__ s4x = (const float4*)sx;
    #pragma unroll
    for (int k = 0; k < EMB / 256; k++) {            // 4 dual-iters
        f4u wa, wb, va, vb;
        wa.f = __ldcs(&w1[lane + 64 * k]);
        wb.f = __ldcs(&w1[lane + 32 + 64 * k]);
        va.f = s4x[lane + 64 * k];
        vb.f = s4x[lane + 32 + 64 * k];
        ffma2(accA, wa.u[0], va.u[0]);
        ffma2(accB, wa.u[1], va.u[1]);
        ffma2(accC, wb.u[0], vb.u[0]);
        ffma2(accD, wb.u[1], vb.u[1]);
    }
    const float4* __restrict__ w2  = (const float4*)(W_hh + (size_t)row * HID);
    const float4* __restrict__ s4h = (const float4*)sh;
    #pragma unroll
    for (int k = 0; k < HID / 256; k++) {            // 8 dual-iters
        f4u wa, wb, va, vb;
        wa.f = __ldcs(&w2[lane + 64 * k]);
        wb.f = __ldcs(&w2[lane + 32 + 64 * k]);
        va.f = s4h[lane + 64 * k];
        vb.f = s4h[lane + 32 + 64 * k];
        ffma2(accA, wa.u[0], va.u[0]);
        ffma2(accB, wa.u[1], va.u[1]);
        ffma2(accC, wb.u[0], vb.u[0]);
        ffma2(accD, wb.u[1], vb.u[1]);
    }
    float a = (f32x2_sum(accA) + f32x2_sum(accB)) +
              (f32x2_sum(accC) + f32x2_sum(accD));

    #pragma unroll
    for (int off = 16; off; off >>= 1)
        a += __shfl_down_sync(0xFFFFFFFFu, a, off);

    if (lane == 0) sg[jl][gate] = a;
    __syncthreads();

    if (threadIdx.x < 2) {
        const int jj = blockIdx.x * 2 + threadIdx.x;
        float ipre = sg[threadIdx.x][0] + b_ih[jj]           + b_hh[jj];
        float fpre = sg[threadIdx.x][1] + b_ih[HID + jj]     + b_hh[HID + jj];
        float gpre = sg[threadIdx.x][2] + b_ih[2 * HID + jj] + b_hh[2 * HID + jj];
        float opre = sg[threadIdx.x][3] + b_ih[3 * HID + jj] + b_hh[3 * HID + jj];

        float ig = 1.0f / (1.0f + expf(-ipre));
        float fg = 1.0f / (1.0f + expf(-fpre));
        float gg = tanhf(gpre);
        float og = 1.0f / (1.0f + expf(-opre));

        float c = fg * g_c[jj] + ig * gg;
        float h = og * tanhf(c);
        g_c[jj]      = c;
        hnext[jj]    = h;
        g_h_half[jj] = __float2half(h);
        atomicAdd(&g_hnorm2[step], h * h);
    }
}

// ---------------------------------------------------------------------------
// Logits: fp16 weights, warp-per-row, HFMA2 accumulation (chain depth 4,
// flushed to fp32 every 16B) -> ~2x fewer fma-pipe instructions per byte.
// Error: |approx-exact| <= 3*2^-10*||w||*||h|| (conv + chain rounding).
// Per-block max key -> g_blockbest; global approx max -> atomicMax g_amax2.
// ---------------------------------------------------------------------------
__global__ void __launch_bounds__(256) logits_kernel(
    const float* __restrict__ b_out,
    float* __restrict__ out,
    int step)
{
    __shared__ __half sh[HID];                       // 4KB
    __shared__ unsigned long long skey[ROWS_PER_BLK];

    {
        const int4* __restrict__ hg = (const int4*)g_h_half;
        ((int4*)sh)[threadIdx.x] = hg[threadIdx.x];
    }
    __syncthreads();

    const int wid  = threadIdx.x >> 5;
    const int lane = threadIdx.x & 31;
    const int row  = blockIdx.x * ROWS_PER_BLK + wid;

    float* __restrict__ orow = out + (size_t)step * VOCAB;

    unsigned long long key = 0ULL;
    if (row < VOCAB) {
        const int4* __restrict__ wp  = (const int4*)(g_Wout_h + (size_t)row * HID);
        const int4* __restrict__ sh4 = (const int4*)sh;

        float a0 = 0.f, a1 = 0.f;
        #pragma unroll
        for (int k = 0; k < 4; k++) {                // 4 iters x 32B/lane
            int4 w0 = __ldcs(&wp[2 * lane + 64 * k]);
            int4 w1 = __ldcs(&wp[2 * lane + 1 + 64 * k]);
            int4 h0 = sh4[2 * lane + 64 * k];
            int4 h1 = sh4[2 * lane + 1 + 64 * k];

            __half2 acc0 = __float2half2_rn(0.f);
            __half2 acc1 = __float2half2_rn(0.f);
            #pragma unroll
            for (int j = 0; j < 4; j++) {
                acc0 = __hfma2(((const __half2*)&w0)[j], ((const __half2*)&h0)[j], acc0);
                acc1 = __hfma2(((const __half2*)&w1)[j], ((const __half2*)&h1)[j], acc1);
            }
            float2 f0 = __half22float2(acc0);
            float2 f1 = __half22float2(acc1);
            a0 += f0.x + f0.y;
            a1 += f1.x + f1.y;
        }
        float a = a0 + a1;
        #pragma unroll
        for (int off = 16; off; off >>= 1)
            a += __shfl_down_sync(0xFFFFFFFFu, a, off);

        if (lane == 0) {
            float logit = a + b_out[row];
            orow[row] = logit;
            key = pack_key(logit, row);
        }
    }
    if (lane == 0) skey[wid] = key;
    __syncthreads();

    if (threadIdx.x == 0) {
        unsigned long long b = 0ULL;
        #pragma unroll
        for (int i = 0; i < ROWS_PER_BLK; i++) if (skey[i] > b) b = skey[i];
        g_blockbest[blockIdx.x] = b;
        if (b) atomicMax(&g_amax2[step], b);
    }
}

// ---------------------------------------------------------------------------
// Argmax fixup (1 block, 512 thr). Single pass over NBLK1 keys:
//  thresh = approx_max - 2E with E = 2^-7*||W_row||max*||h|| (2.9x margin
//  over the proven 3*2^-10 bound). Qualifying blocks' rows inspected,
//  candidates recomputed exactly in fp32 -> exact first-index argmax.
// ---------------------------------------------------------------------------
__global__ void __launch_bounds__(512) argmax_fixup(
    const float* __restrict__ W_out,
    const float* __restrict__ b_out,
    float* __restrict__ out,
    int step)
{
    __shared__ int s_ncand;
    __shared__ int s_cand[MAXCAND];
    __shared__ unsigned long long s_ckey[MAXCAND];

    const int tid = threadIdx.x;
    if (tid == 0) s_ncand = 0;
    __syncthreads();

    const float E = 0.0078125f *              // 2^-7
                    sqrtf(__uint_as_float(g_wmax2) * g_hnorm2[step]);
    const float thresh = unpack_val(g_amax2[step]) - 2.0f * E;

    float* __restrict__ orow = out + (size_t)step * VOCAB;

    for (int b = tid; b < NBLK1; b += 512) {
        unsigned long long k = __ldcg(&g_blockbest[b]);
        if (k != 0ULL && unpack_val(k) >= thresh) {
            const int r0 = b * ROWS_PER_BLK;
            const int r1 = (r0 + ROWS_PER_BLK < VOCAB) ? r0 + ROWS_PER_BLK : VOCAB;
            for (int r = r0; r < r1; r++) {
                float v = __ldcg(&orow[r]);
                if (v >= thresh) {
                    int p = atomicAdd(&s_ncand, 1);
                    if (p < MAXCAND) s_cand[p] = r;
                }
            }
        }
    }
    __syncthreads();

    int nc = s_ncand; if (nc > MAXCAND) nc = MAXCAND;

    const int wid  = tid >> 5;
    const int lane = tid & 31;
    const float4* __restrict__ hp32 = (const float4*)g_h[(step + 1) & 1];

    for (int ci = wid; ci < nc; ci += 16) {
        const int r = s_cand[ci];
        const float4* __restrict__ wp = (const float4*)(W_out + (size_t)r * HID);
        float a = 0.f;
        #pragma unroll
        for (int k = 0; k < HID / 128; k++) {
            float4 w = wp[lane + 32 * k];
            float4 v = hp32[lane + 32 * k];
            a += w.x * v.x + w.y * v.y + w.z * v.z + w.w * v.w;
        }
        #pragma unroll
        for (int off = 16; off; off >>= 1)
            a += __shfl_down_sync(0xFFFFFFFFu, a, off);
        if (lane == 0) {
            float logit = a + b_out[r];
            orow[r] = logit;                          // exact overwrite
            s_ckey[ci] = pack_key(logit, r);
        }
    }
    __syncthreads();

    if (tid == 0) {
        unsigned long long b = 0ULL;
        for (int i = 0; i < nc; i++) if (s_ckey[i] > b) b = s_ckey[i];
        g_amax[step] = b;
    }
}

// ---------------------------------------------------------------------------
extern "C" void kernel_launch(void* const* d_in, const int* in_sizes, int n_in,
                              void* d_out, int out_size) {
    const float* emb   = (const float*)d_in[0];
    const float* W_ih  = (const float*)d_in[1];
    const float* W_hh  = (const float*)d_in[2];
    const float* b_ih  = (const float*)d_in[3];
    const float* b_hh  = (const float*)d_in[4];
    const float* W_out = (const float*)d_in[5];
    const float* b_out = (const float*)d_in[6];
    float* out = (float*)d_out;

    init_kernel<<<(HID + 255) / 256, 256>>>();
    convert_wout<<<2048, 256>>>(W_out);

    for (int t = 0; t < T; t++) {
        lstm_step_kernel<<<HID / 2, 256>>>(emb, W_ih, W_hh, b_ih, b_hh, t);
        logits_kernel<<<NBLK1, 256>>>(b_out, out, t);
        argmax_fixup<<<1, 512>>>(W_out, b_out, out, t);
    }
}

// round 12
// speedup vs baseline: 1.7242x; 1.0089x over previous
#include <cuda_runtime.h>
#include <cuda_fp16.h>
#include <math.h>

#define EMB   1024
#define HID   2048
#define VOCAB 50257
#define T     256
#define ROWS_PER_BLK 8
#define NBLK1 ((VOCAB + ROWS_PER_BLK - 1) / ROWS_PER_BLK)   // 6283 logits blocks
#define NHHB  (4 * HID / ROWS_PER_BLK)                       // 1024 hh blocks
#define MAXCAND 256

// Persistent device state (allocation-free scratch).
__device__ float g_h[2][HID];
__device__ __half g_h_half[HID];
__device__ float g_c[HID];
__device__ float g_hh[4 * HID];                   // W_hh @ h  precomputed for next step
__device__ unsigned long long g_amax[T];          // EXACT packed argmax per step
__device__ unsigned long long g_amax2[T];         // approx global max key per step
__device__ unsigned long long g_blockbest[NBLK1]; // per-block approx max keys
__device__ float g_hnorm2[T];                     // ||h||^2 per step
__device__ unsigned g_wmax2;                      // max row-norm^2 of W_out (ordered uint)
__device__ __half g_Wout_h[VOCAB * HID];          // fp16 W_out (~206MB)

__device__ __forceinline__ unsigned long long pack_key(float v, int row) {
    unsigned ub = __float_as_uint(v);
    ub = (ub & 0x80000000u) ? ~ub : (ub | 0x80000000u);
    return ((unsigned long long)ub << 32) |
           (unsigned long long)(0xFFFFFFFFu - (unsigned)row);
}
__device__ __forceinline__ float unpack_val(unsigned long long key) {
    unsigned t = (unsigned)(key >> 32);
    unsigned orig = (t & 0x80000000u) ? (t ^ 0x80000000u) : ~t;
    return __uint_as_float(orig);
}

// Packed f32x2 FMA (Blackwell FFMA2).
__device__ __forceinline__ void ffma2(unsigned long long& acc,
                                      unsigned long long a, unsigned long long b) {
    asm("fma.rn.f32x2 %0, %1, %2, %3;" : "=l"(acc) : "l"(a), "l"(b), "l"(acc));
}
__device__ __forceinline__ float f32x2_sum(unsigned long long v) {
    float2 f = *reinterpret_cast<float2*>(&v);
    return f.x + f.y;
}
union f4u { float4 f; unsigned long long u[2]; };

// ---------------------------------------------------------------------------
// Convert W_out to fp16 AND compute max row-norm^2 (block-per-row).
// ---------------------------------------------------------------------------
__global__ void __launch_bounds__(256) convert_wout(const float* __restrict__ W) {
    __shared__ float swsum[8];
    float maxn = 0.0f;

    for (int r = blockIdx.x; r < VOCAB; r += gridDim.x) {
        const float4* __restrict__ src = (const float4*)(W + (size_t)r * HID);
        __half2* __restrict__ dst = (__half2*)(g_Wout_h + (size_t)r * HID);
        float ss = 0.0f;
        #pragma unroll
        for (int i = threadIdx.x; i < HID / 4; i += 256) {
            float4 v = src[i];
            dst[2 * i]     = __floats2half2_rn(v.x, v.y);
            dst[2 * i + 1] = __floats2half2_rn(v.z, v.w);
            ss += v.x * v.x + v.y * v.y + v.z * v.z + v.w * v.w;
        }
        #pragma unroll
        for (int off = 16; off; off >>= 1)
            ss += __shfl_down_sync(0xFFFFFFFFu, ss, off);
        if ((threadIdx.x & 31) == 0) swsum[threadIdx.x >> 5] = ss;
        __syncthreads();
        if (threadIdx.x == 0) {
            float tot = 0.0f;
            #pragma unroll
            for (int i = 0; i < 8; i++) tot += swsum[i];
            if (tot > maxn) maxn = tot;
        }
        __syncthreads();
    }
    if (threadIdx.x == 0)
        atomicMax(&g_wmax2, __float_as_uint(maxn));
}

__global__ void init_kernel() {
    int i = blockIdx.x * blockDim.x + threadIdx.x;   // grid covers 8192
    if (i < HID) {
        g_h[0][i] = 0.0f;
        g_h[1][i] = 0.0f;
        g_h_half[i] = __float2half(0.0f);
        g_c[i]    = 0.0f;
    }
    if (i < 4 * HID) g_hh[i] = 0.0f;
    if (i < T) { g_amax[i] = 0ULL; g_amax2[i] = 0ULL; g_hnorm2[i] = 0.0f; }
    if (i == 0) g_wmax2 = 0u;
}

// ---------------------------------------------------------------------------
// step_rest: gates = W_ih @ x + g_hh (precomputed W_hh @ h) + biases, then
// LSTM cell. Warp-per-(gate,j), FFMA2 packed math. Only 32MB of traffic.
// ---------------------------------------------------------------------------
__global__ void __launch_bounds__(256) step_rest_kernel(
    const float* __restrict__ emb,
    const float* __restrict__ W_ih,
    const float* __restrict__ b_ih,
    const float* __restrict__ b_hh,
    int step)
{
    __shared__ float sx[EMB];
    __shared__ float sg[2][4];

    int tok = 0;
    if (step > 0)
        tok = (int)(0xFFFFFFFFu - (unsigned)(g_amax[step - 1] & 0xFFFFFFFFull));

    float* __restrict__ hnext = g_h[(step + 1) & 1];

    const float* __restrict__ xrow = emb + (size_t)tok * EMB;
    for (int i = threadIdx.x; i < EMB; i += 256) sx[i] = xrow[i];
    __syncthreads();

    const int wid  = threadIdx.x >> 5;
    const int lane = threadIdx.x & 31;
    const int jl   = wid >> 2;
    const int gate = wid & 3;
    const int j    = blockIdx.x * 2 + jl;
    const int row  = gate * HID + j;

    unsigned long long accA = 0ULL, accB = 0ULL, accC = 0ULL, accD = 0ULL;

    const float4* __restrict__ w1  = (const float4*)(W_ih + (size_t)row * EMB);
    const float4* __restrict__ s4x = (const float4*)sx;
    #pragma unroll
    for (int k = 0; k < EMB / 256; k++) {            // 4 dual-iters
        f4u wa, wb, va, vb;
        wa.f = __ldcs(&w1[lane + 64 * k]);
        wb.f = __ldcs(&w1[lane + 32 + 64 * k]);
        va.f = s4x[lane + 64 * k];
        vb.f = s4x[lane + 32 + 64 * k];
        ffma2(accA, wa.u[0], va.u[0]);
        ffma2(accB, wa.u[1], va.u[1]);
        ffma2(accC, wb.u[0], vb.u[0]);
        ffma2(accD, wb.u[1], vb.u[1]);
    }
    float a = (f32x2_sum(accA) + f32x2_sum(accB)) +
              (f32x2_sum(accC) + f32x2_sum(accD));

    #pragma unroll
    for (int off = 16; off; off >>= 1)
        a += __shfl_down_sync(0xFFFFFFFFu, a, off);

    if (lane == 0) sg[jl][gate] = a + g_hh[row];     // add precomputed hh term
    __syncthreads();

    if (threadIdx.x < 2) {
        const int jj = blockIdx.x * 2 + threadIdx.x;
        float ipre = sg[threadIdx.x][0] + b_ih[jj]           + b_hh[jj];
        float fpre = sg[threadIdx.x][1] + b_ih[HID + jj]     + b_hh[HID + jj];
        float gpre = sg[threadIdx.x][2] + b_ih[2 * HID + jj] + b_hh[2 * HID + jj];
        float opre = sg[threadIdx.x][3] + b_ih[3 * HID + jj] + b_hh[3 * HID + jj];

        float ig = 1.0f / (1.0f + expf(-ipre));
        float fg = 1.0f / (1.0f + expf(-fpre));
        float gg = tanhf(gpre);
        float og = 1.0f / (1.0f + expf(-opre));

        float c = fg * g_c[jj] + ig * gg;
        float h = og * tanhf(c);
        g_c[jj]      = c;
        hnext[jj]    = h;
        g_h_half[jj] = __float2half(h);
        atomicAdd(&g_hnorm2[step], h * h);
    }
}

// ---------------------------------------------------------------------------
// Fused kernel: blocks [0, NBLK1) compute fp16 logits (warp-per-row, HFMA2);
// blocks [NBLK1, NBLK1+NHHB) compute hh_part(t+1) = W_hh @ h(t) in fp32.
// Both roles depend only on h(t) -> the 64MB W_hh stream leaves the serial
// critical path and merges with the 103MB W_out stream in ONE launch.
// ---------------------------------------------------------------------------
__global__ void __launch_bounds__(256) fused_kernel(
    const float* __restrict__ W_hh,
    const float* __restrict__ b_out,
    float* __restrict__ out,
    int step)
{
    __shared__ float sbuf[HID];                      // 8KB; logits role uses 4KB as half
    __shared__ unsigned long long skey[ROWS_PER_BLK];

    const int wid  = threadIdx.x >> 5;
    const int lane = threadIdx.x & 31;

    if (blockIdx.x < NBLK1) {
        // ---------------- logits role ----------------
        __half* sh = (__half*)sbuf;
        ((int4*)sh)[threadIdx.x] = ((const int4*)g_h_half)[threadIdx.x];  // 4KB
        __syncthreads();

        const int row = blockIdx.x * ROWS_PER_BLK + wid;
        float* __restrict__ orow = out + (size_t)step * VOCAB;

        unsigned long long key = 0ULL;
        if (row < VOCAB) {
            const int4* __restrict__ wp  = (const int4*)(g_Wout_h + (size_t)row * HID);
            const int4* __restrict__ sh4 = (const int4*)sh;

            float a0 = 0.f, a1 = 0.f;
            #pragma unroll
            for (int k = 0; k < 4; k++) {            // 4 iters x 32B/lane
                int4 w0 = __ldcs(&wp[2 * lane + 64 * k]);
                int4 w1 = __ldcs(&wp[2 * lane + 1 + 64 * k]);
                int4 h0 = sh4[2 * lane + 64 * k];
                int4 h1 = sh4[2 * lane + 1 + 64 * k];

                __half2 acc0 = __float2half2_rn(0.f);
                __half2 acc1 = __float2half2_rn(0.f);
                #pragma unroll
                for (int jq = 0; jq < 4; jq++) {
                    acc0 = __hfma2(((const __half2*)&w0)[jq], ((const __half2*)&h0)[jq], acc0);
                    acc1 = __hfma2(((const __half2*)&w1)[jq], ((const __half2*)&h1)[jq], acc1);
                }
                float2 f0 = __half22float2(acc0);
                float2 f1 = __half22float2(acc1);
                a0 += f0.x + f0.y;
                a1 += f1.x + f1.y;
            }
            float a = a0 + a1;
            #pragma unroll
            for (int off = 16; off; off >>= 1)
                a += __shfl_down_sync(0xFFFFFFFFu, a, off);

            if (lane == 0) {
                float logit = a + b_out[row];
                orow[row] = logit;
                key = pack_key(logit, row);
            }
        }
        if (lane == 0) skey[wid] = key;
        __syncthreads();

        if (threadIdx.x == 0) {
            unsigned long long b = 0ULL;
            #pragma unroll
            for (int i = 0; i < ROWS_PER_BLK; i++) if (skey[i] > b) b = skey[i];
            g_blockbest[blockIdx.x] = b;
            if (b) atomicMax(&g_amax2[step], b);
        }
    } else {
        // ---------------- W_hh @ h role (fp32) ----------------
        const float4* __restrict__ hg = (const float4*)g_h[(step + 1) & 1];
        float4* s4 = (float4*)sbuf;
        s4[threadIdx.x]       = hg[threadIdx.x];      // 512 float4 = 8KB
        s4[threadIdx.x + 256] = hg[threadIdx.x + 256];
        __syncthreads();

        const int row = (int)(blockIdx.x - NBLK1) * ROWS_PER_BLK + wid;  // 0..8191
        const float4* __restrict__ w2 = (const float4*)(W_hh + (size_t)row * HID);

        unsigned long long accA = 0ULL, accB = 0ULL, accC = 0ULL, accD = 0ULL;
        #pragma unroll
        for (int k = 0; k < HID / 256; k++) {        // 8 dual-iters
            f4u wa, wb, va, vb;
            wa.f = __ldcs(&w2[lane + 64 * k]);
            wb.f = __ldcs(&w2[lane + 32 + 64 * k]);
            va.f = s4[lane + 64 * k];
            vb.f = s4[lane + 32 + 64 * k];
            ffma2(accA, wa.u[0], va.u[0]);
            ffma2(accB, wa.u[1], va.u[1]);
            ffma2(accC, wb.u[0], vb.u[0]);
            ffma2(accD, wb.u[1], vb.u[1]);
        }
        float a = (f32x2_sum(accA) + f32x2_sum(accB)) +
                  (f32x2_sum(accC) + f32x2_sum(accD));

        #pragma unroll
        for (int off = 16; off; off >>= 1)
            a += __shfl_down_sync(0xFFFFFFFFu, a, off);

        if (lane == 0) g_hh[row] = a;
    }
}

// ---------------------------------------------------------------------------
// Argmax fixup (1 block, 512 thr). thresh = approx_max - 2E with
// E = 2^-7*||W_row||max*||h|| (2.9x margin over the proven HFMA2-chain
// bound 3*2^-10*||w||*||h||). Candidates recomputed exactly in fp32.
// ---------------------------------------------------------------------------
__global__ void __launch_bounds__(512) argmax_fixup(
    const float* __restrict__ W_out,
    const float* __restrict__ b_out,
    float* __restrict__ out,
    int step)
{
    __shared__ int s_ncand;
    __shared__ int s_cand[MAXCAND];
    __shared__ unsigned long long s_ckey[MAXCAND];

    const int tid = threadIdx.x;
    if (tid == 0) s_ncand = 0;
    __syncthreads();

    const float E = 0.0078125f *              // 2^-7
                    sqrtf(__uint_as_float(g_wmax2) * g_hnorm2[step]);
    const float thresh = unpack_val(g_amax2[step]) - 2.0f * E;

    float* __restrict__ orow = out + (size_t)step * VOCAB;

    for (int b = tid; b < NBLK1; b += 512) {
        unsigned long long k = __ldcg(&g_blockbest[b]);
        if (k != 0ULL && unpack_val(k) >= thresh) {
            const int r0 = b * ROWS_PER_BLK;
            const int r1 = (r0 + ROWS_PER_BLK < VOCAB) ? r0 + ROWS_PER_BLK : VOCAB;
            for (int r = r0; r < r1; r++) {
                float v = __ldcg(&orow[r]);
                if (v >= thresh) {
                    int p = atomicAdd(&s_ncand, 1);
                    if (p < MAXCAND) s_cand[p] = r;
                }
            }
        }
    }
    __syncthreads();

    int nc = s_ncand; if (nc > MAXCAND) nc = MAXCAND;

    const int wid  = tid >> 5;
    const int lane = tid & 31;
    const float4* __restrict__ hp32 = (const float4*)g_h[(step + 1) & 1];

    for (int ci = wid; ci < nc; ci += 16) {
        const int r = s_cand[ci];
        const float4* __restrict__ wp = (const float4*)(W_out + (size_t)r * HID);
        float a = 0.f;
        #pragma unroll
        for (int k = 0; k < HID / 128; k++) {
            float4 w = wp[lane + 32 * k];
            float4 v = hp32[lane + 32 * k];
            a += w.x * v.x + w.y * v.y + w.z * v.z + w.w * v.w;
        }
        #pragma unroll
        for (int off = 16; off; off >>= 1)
            a += __shfl_down_sync(0xFFFFFFFFu, a, off);
        if (lane == 0) {
            float logit = a + b_out[r];
            orow[r] = logit;                          // exact overwrite
            s_ckey[ci] = pack_key(logit, r);
        }
    }
    __syncthreads();

    if (tid == 0) {
        unsigned long long b = 0ULL;
        for (int i = 0; i < nc; i++) if (s_ckey[i] > b) b = s_ckey[i];
        g_amax[step] = b;
    }
}

// ---------------------------------------------------------------------------
extern "C" void kernel_launch(void* const* d_in, const int* in_sizes, int n_in,
                              void* d_out, int out_size) {
    const float* emb   = (const float*)d_in[0];
    const float* W_ih  = (const float*)d_in[1];
    const float* W_hh  = (const float*)d_in[2];
    const float* b_ih  = (const float*)d_in[3];
    const float* b_hh  = (const float*)d_in[4];
    const float* W_out = (const float*)d_in[5];
    const float* b_out = (const float*)d_in[6];
    float* out = (float*)d_out;

    init_kernel<<<32, 256>>>();
    convert_wout<<<2048, 256>>>(W_out);

    for (int t = 0; t < T; t++) {
        step_rest_kernel<<<HID / 2, 256>>>(emb, W_ih, b_ih, b_hh, t);
        fused_kernel<<<NBLK1 + NHHB, 256>>>(W_hh, b_out, out, t);
        argmax_fixup<<<1, 512>>>(W_out, b_out, out, t);
    }
}